// round 2
// baseline (speedup 1.0000x reference)
#include <cuda_runtime.h>
#include <cstdint>
#include <cstddef>

#define TT 256
#define BB 32
#define HH 256
#define LL 4
#define VV 32000
#define HB (HH*BB)
#define NCTA 128

__device__ float g_h[LL][(size_t)(TT+1)*HB];   // [l][t][k][b]; row t=0 stays zero
__device__ unsigned g_bar_count;               // self-resetting
__device__ unsigned g_bar_gen;                 // monotonic (replay-safe)

__device__ __forceinline__ unsigned long long pk2(float lo, float hi) {
    unsigned long long r;
    asm("mov.b64 %0, {%1, %2};" : "=l"(r) : "r"(__float_as_uint(lo)), "r"(__float_as_uint(hi)));
    return r;
}
__device__ __forceinline__ unsigned long long fma2(unsigned long long a, unsigned long long b,
                                                   unsigned long long c) {
    unsigned long long d;
    asm("fma.rn.f32x2 %0, %1, %2, %3;" : "=l"(d) : "l"(a), "l"(b), "l"(c));
    return d;
}
__device__ __forceinline__ void upk2(unsigned long long v, float& lo, float& hi) {
    unsigned a, b;
    asm("mov.b64 {%0, %1}, %2;" : "=r"(a), "=r"(b) : "l"(v));
    lo = __uint_as_float(a); hi = __uint_as_float(b);
}
__device__ __forceinline__ float upks(unsigned long long v) { float a,b; upk2(v,a,b); return a+b; }

// ================= RNN: persistent wavefront =================
// 128 CTAs = 4 layers x 32 n-slices (8 neurons each). 256 thr = 8 k-warps x 32 batch.
__global__ void __launch_bounds__(256) rnn_kernel(const int* __restrict__ tokens,
                                                  const float* __restrict__ emb,
                                                  const float* __restrict__ W_ih,
                                                  const float* __restrict__ W_hh,
                                                  const float* __restrict__ b_ih,
                                                  const float* __restrict__ b_hh,
                                                  float* out_hidden, int write_hidden) {
    const int cta = blockIdx.x;
    const int l = cta >> 5;
    const int n0 = (cta & 31) * 8;
    __shared__ float wih_s[8][HH], whh_s[8][HH];
    __shared__ float part[8][8][BB];
    __shared__ float bias_s[8];
    const int tid = threadIdx.x;

    for (int i = tid; i < 8*HH; i += 256) {
        int j = i / HH, k = i % HH;
        wih_s[j][k] = W_ih[((size_t)l*HH + n0 + j)*HH + k];
        whh_s[j][k] = W_hh[((size_t)l*HH + n0 + j)*HH + k];
    }
    if (tid < 8) bias_s[tid] = b_ih[l*HH + n0 + tid] + b_hh[l*HH + n0 + tid];
    __syncthreads();

    const int wi = tid >> 5, b = tid & 31;
    const int kb = wi * 32;

    for (int w = 0; w < TT + LL - 1; w++) {
        const int t = w - l;
        if (t >= 0 && t < TT) {
            const float* hp = g_h[l] + (size_t)t * HB;                      // own h(t-1)
            const float* xp;                                                 // input x(t)
            if (l == 0) xp = emb + (size_t)tokens[t*BB + b] * HH;           // [k] contiguous
            else        xp = g_h[l-1] + (size_t)(t+1) * HB;                 // [k][b]
            unsigned long long acc[8];
            #pragma unroll
            for (int j = 0; j < 8; j++) acc[j] = 0ull;

            #pragma unroll
            for (int kk = 0; kk < 32; kk += 2) {
                const int k = kb + kk;
                unsigned long long hv = pk2(hp[k*BB + b], hp[(k+1)*BB + b]);
                unsigned long long xv;
                if (l == 0) { float2 e = *(const float2*)(xp + k); xv = pk2(e.x, e.y); }
                else        xv = pk2(xp[k*BB + b], xp[(k+1)*BB + b]);
                #pragma unroll
                for (int j = 0; j < 8; j++) {
                    float2 wh = *(const float2*)&whh_s[j][k];
                    float2 wx = *(const float2*)&wih_s[j][k];
                    acc[j] = fma2(hv, pk2(wh.x, wh.y), acc[j]);
                    acc[j] = fma2(xv, pk2(wx.x, wx.y), acc[j]);
                }
            }
            #pragma unroll
            for (int j = 0; j < 8; j++) part[wi][j][b] = upks(acc[j]);
            __syncthreads();
            float p = bias_s[wi];
            #pragma unroll
            for (int w2 = 0; w2 < 8; w2++) p += part[w2][wi][b];
            g_h[l][(size_t)(t+1)*HB + (n0 + wi)*BB + b] = tanhf(p);
        }
        // grid barrier (generation-based)
        __syncthreads();
        if (tid == 0) {
            __threadfence();
            unsigned gen = *(volatile unsigned*)&g_bar_gen;
            if (atomicAdd(&g_bar_count, 1u) == NCTA - 1u) {
                g_bar_count = 0u;
                __threadfence();
                atomicAdd(&g_bar_gen, 1u);
            } else {
                while (*(volatile unsigned*)&g_bar_gen == gen) { }
            }
            __threadfence();
        }
        __syncthreads();
    }

    if (write_hidden)   // [L][B][H]
        out_hidden[(size_t)l*BB*HH + (size_t)b*HH + (n0 + wi)] =
            g_h[l][(size_t)TT*HB + (n0 + wi)*BB + b];
}

// ================= Decoder GEMM: out[m][v] = X[m][:].dec_W[v][:] + dec_b[v] =================
#define BM 128
#define BN 128
#define BK 16
__global__ void __launch_bounds__(256) dec_kernel(const float* __restrict__ dec_W,
                                                  const float* __restrict__ dec_b,
                                                  float* __restrict__ out) {
    __shared__ float As[2][BK][BM+4];
    __shared__ float Bs[2][BK][BN+4];
    const int tid = threadIdx.x;
    const int v0 = blockIdx.x * BN;
    const int m0 = blockIdx.y * BM;
    const int tx = tid & 15, ty = tid >> 4;
    const float* X = g_h[LL-1];
    const int t0 = m0 >> 5;                     // m = t*32 + b

    unsigned long long acc[8][4];
    #pragma unroll
    for (int i = 0; i < 8; i++)
        #pragma unroll
        for (int j = 0; j < 4; j++) acc[i][j] = 0ull;

    #pragma unroll
    for (int r = 0; r < 8; r++) {
        int lin = tid + r*256, ml = lin & 127, kl = lin >> 7;
        As[0][kl][ml] = X[(size_t)(t0 + (ml >> 5) + 1)*HB + kl*BB + (ml & 31)];
    }
    #pragma unroll
    for (int r = 0; r < 8; r++) {
        int lin = tid + r*256, kl = lin & 15, vl = lin >> 4;
        Bs[0][kl][vl] = dec_W[(size_t)(v0 + vl)*HH + kl];
    }
    __syncthreads();

    #pragma unroll 1
    for (int ks = 0; ks < HH/BK; ks++) {
        const int cur = ks & 1, nxt = cur ^ 1;
        float ra[8], rb[8];
        const bool more = (ks + 1 < HH/BK);
        if (more) {
            const int k0 = (ks + 1) * BK;
            #pragma unroll
            for (int r = 0; r < 8; r++) {
                int lin = tid + r*256, ml = lin & 127, kl = lin >> 7;
                ra[r] = X[(size_t)(t0 + (ml >> 5) + 1)*HB + (k0 + kl)*BB + (ml & 31)];
            }
            #pragma unroll
            for (int r = 0; r < 8; r++) {
                int lin = tid + r*256, kl = lin & 15, vl = lin >> 4;
                rb[r] = dec_W[(size_t)(v0 + vl)*HH + k0 + kl];
            }
        }
        #pragma unroll
        for (int k = 0; k < BK; k++) {
            float4 a0 = *(const float4*)&As[cur][k][ty*8];
            float4 a1 = *(const float4*)&As[cur][k][ty*8 + 4];
            float4 b0 = *(const float4*)&Bs[cur][k][tx*8];
            float4 b1 = *(const float4*)&Bs[cur][k][tx*8 + 4];
            unsigned long long bp0 = pk2(b0.x, b0.y), bp1 = pk2(b0.z, b0.w);
            unsigned long long bp2 = pk2(b1.x, b1.y), bp3 = pk2(b1.z, b1.w);
            float am[8] = {a0.x, a0.y, a0.z, a0.w, a1.x, a1.y, a1.z, a1.w};
            #pragma unroll
            for (int mi = 0; mi < 8; mi++) {
                unsigned long long av = pk2(am[mi], am[mi]);
                acc[mi][0] = fma2(av, bp0, acc[mi][0]);
                acc[mi][1] = fma2(av, bp1, acc[mi][1]);
                acc[mi][2] = fma2(av, bp2, acc[mi][2]);
                acc[mi][3] = fma2(av, bp3, acc[mi][3]);
            }
        }
        if (more) {
            __syncthreads();
            #pragma unroll
            for (int r = 0; r < 8; r++) {
                int lin = tid + r*256;
                As[nxt][lin >> 7][lin & 127] = ra[r];
            }
            #pragma unroll
            for (int r = 0; r < 8; r++) {
                int lin = tid + r*256;
                Bs[nxt][lin & 15][lin >> 4] = rb[r];
            }
            __syncthreads();
        }
    }

    const int vb = v0 + tx*8;
    float4 db0 = *(const float4*)&dec_b[vb];
    float4 db1 = *(const float4*)&dec_b[vb + 4];
    #pragma unroll
    for (int mi = 0; mi < 8; mi++) {
        const int m = m0 + ty*8 + mi;
        float o[8];
        upk2(acc[mi][0], o[0], o[1]); upk2(acc[mi][1], o[2], o[3]);
        upk2(acc[mi][2], o[4], o[5]); upk2(acc[mi][3], o[6], o[7]);
        float4 s0 = {o[0]+db0.x, o[1]+db0.y, o[2]+db0.z, o[3]+db0.w};
        float4 s1 = {o[4]+db1.x, o[5]+db1.y, o[6]+db1.z, o[7]+db1.w};
        *(float4*)&out[(size_t)m*VV + vb]     = s0;
        *(float4*)&out[(size_t)m*VV + vb + 4] = s1;
    }
}

extern "C" void kernel_launch(void* const* d_in, const int* in_sizes, int n_in,
                              void* d_out, int out_size) {
    const int*   tokens = (const int*)  d_in[0];
    const float* emb    = (const float*)d_in[1];
    const float* W_ih   = (const float*)d_in[2];
    const float* W_hh   = (const float*)d_in[3];
    const float* b_ih   = (const float*)d_in[4];
    const float* b_hh   = (const float*)d_in[5];
    const float* dec_W  = (const float*)d_in[6];
    const float* dec_b  = (const float*)d_in[7];
    float* out = (float*)d_out;

    const size_t dec_elems = (size_t)TT * BB * VV;
    const int write_hidden = ((size_t)out_size >= dec_elems + (size_t)LL*BB*HH) ? 1 : 0;
    float* out_hidden = out + dec_elems;

    rnn_kernel<<<NCTA, 256>>>(tokens, emb, W_ih, W_hh, b_ih, b_hh, out_hidden, write_hidden);
    dim3 grid(VV / BN, (TT * BB) / BM);
    dec_kernel<<<grid, 256>>>(dec_W, dec_b, out);
}

// round 4
// speedup vs baseline: 1.5779x; 1.5779x over previous
#include <cuda_runtime.h>
#include <cuda_bf16.h>
#include <cstdint>
#include <cstddef>

#define TT 256
#define BB 32
#define HH 256
#define LL 4
#define VV 32000
#define HB (HH*BB)
#define NCTA 128

#define DK   768          // extended K: [hi | lo | hi] x [hi | hi | lo]
#define DBM  128
#define DBN  256
#define DBK  64
#define KITERS (DK/DBK)   // 12
#define MT (8192/DBM)     // 64
#define NT (VV/DBN)       // 125

// ---------------- device scratch ----------------
__device__ float g_h[LL][(size_t)(TT+1)*HB];   // [l][t][k][b]; row t=0 stays zero
__device__ unsigned g_bar_count;
__device__ unsigned g_bar_gen;
__device__ __nv_bfloat16 g_Aext[(size_t)8192*DK];   // 12.6 MB
__device__ __nv_bfloat16 g_Bext[(size_t)VV*DK];     // 49.2 MB

// ---------------- helpers ----------------
__device__ __forceinline__ uint32_t smem_u32(const void* p) {
    uint32_t a;
    asm("{ .reg .u64 t; cvta.to.shared.u64 t, %1; cvt.u32.u64 %0, t; }" : "=r"(a) : "l"(p));
    return a;
}
#define CP_ASYNC16(dst, src) asm volatile("cp.async.cg.shared.global [%0], [%1], 16;" :: "r"(dst), "l"(src))
#define CP_COMMIT()          asm volatile("cp.async.commit_group;" ::: "memory")
#define CP_WAIT(n)           asm volatile("cp.async.wait_group %0;" :: "n"(n) : "memory")
#define LDSM4(r0,r1,r2,r3,addr) \
    asm volatile("ldmatrix.sync.aligned.m8n8.x4.shared.b16 {%0,%1,%2,%3}, [%4];" \
                 : "=r"(r0),"=r"(r1),"=r"(r2),"=r"(r3) : "r"(addr))
#define MMA16816(d, a, b0, b1) \
    asm volatile("mma.sync.aligned.m16n8k16.row.col.f32.bf16.bf16.f32 " \
                 "{%0,%1,%2,%3},{%4,%5,%6,%7},{%8,%9},{%0,%1,%2,%3};" \
                 : "+f"((d)[0]),"+f"((d)[1]),"+f"((d)[2]),"+f"((d)[3]) \
                 : "r"((a)[0]),"r"((a)[1]),"r"((a)[2]),"r"((a)[3]), "r"(b0),"r"(b1))

// f32x2 helpers (RNN)
__device__ __forceinline__ unsigned long long pk2(float lo, float hi) {
    unsigned long long r;
    asm("mov.b64 %0, {%1, %2};" : "=l"(r) : "r"(__float_as_uint(lo)), "r"(__float_as_uint(hi)));
    return r;
}
__device__ __forceinline__ unsigned long long fma2(unsigned long long a, unsigned long long b,
                                                   unsigned long long c) {
    unsigned long long d;
    asm("fma.rn.f32x2 %0, %1, %2, %3;" : "=l"(d) : "l"(a), "l"(b), "l"(c));
    return d;
}
__device__ __forceinline__ float upks(unsigned long long v) {
    unsigned a, b;
    asm("mov.b64 {%0, %1}, %2;" : "=r"(a), "=r"(b) : "l"(v));
    return __uint_as_float(a) + __uint_as_float(b);
}

// ================= bf16-split conversions =================
__global__ void __launch_bounds__(256) convW_kernel(const float* __restrict__ W) {
    const size_t stride = (size_t)gridDim.x * 256;
    for (size_t e = (size_t)blockIdx.x * 256 + threadIdx.x; e < (size_t)VV * HH; e += stride) {
        const int k = (int)(e & 255);
        const size_t v = e >> 8;
        float w = W[e];
        __nv_bfloat16 hi = __float2bfloat16(w);
        __nv_bfloat16 lo = __float2bfloat16(w - __bfloat162float(hi));
        __nv_bfloat16* row = g_Bext + v * DK;
        row[k] = hi; row[256 + k] = hi; row[512 + k] = lo;
    }
}
__global__ void __launch_bounds__(256) convX_kernel() {
    const size_t stride = (size_t)gridDim.x * 256;
    for (size_t e = (size_t)blockIdx.x * 256 + threadIdx.x; e < (size_t)8192 * HH; e += stride) {
        const int m = (int)(e & 8191);
        const int k = (int)(e >> 13);
        const int t = m >> 5, b = m & 31;
        float x = g_h[LL-1][(size_t)(t + 1) * HB + k * BB + b];
        __nv_bfloat16 hi = __float2bfloat16(x);
        __nv_bfloat16 lo = __float2bfloat16(x - __bfloat162float(hi));
        __nv_bfloat16* row = g_Aext + (size_t)m * DK;
        row[k] = hi; row[256 + k] = lo; row[512 + k] = hi;
    }
}

// ================= RNN: persistent wavefront (unchanged) =================
__global__ void __launch_bounds__(256) rnn_kernel(const int* __restrict__ tokens,
                                                  const float* __restrict__ emb,
                                                  const float* __restrict__ W_ih,
                                                  const float* __restrict__ W_hh,
                                                  const float* __restrict__ b_ih,
                                                  const float* __restrict__ b_hh,
                                                  float* out_hidden, int write_hidden) {
    const int cta = blockIdx.x;
    const int l = cta >> 5;
    const int n0 = (cta & 31) * 8;
    __shared__ float wih_s[8][HH], whh_s[8][HH];
    __shared__ float part[8][8][BB];
    __shared__ float bias_s[8];
    const int tid = threadIdx.x;

    for (int i = tid; i < 8*HH; i += 256) {
        int j = i / HH, k = i % HH;
        wih_s[j][k] = W_ih[((size_t)l*HH + n0 + j)*HH + k];
        whh_s[j][k] = W_hh[((size_t)l*HH + n0 + j)*HH + k];
    }
    if (tid < 8) bias_s[tid] = b_ih[l*HH + n0 + tid] + b_hh[l*HH + n0 + tid];
    __syncthreads();

    const int wi = tid >> 5, b = tid & 31;
    const int kb = wi * 32;

    for (int w = 0; w < TT + LL - 1; w++) {
        const int t = w - l;
        if (t >= 0 && t < TT) {
            const float* hp = g_h[l] + (size_t)t * HB;
            const float* xp;
            if (l == 0) xp = emb + (size_t)tokens[t*BB + b] * HH;
            else        xp = g_h[l-1] + (size_t)(t+1) * HB;
            unsigned long long acc[8];
            #pragma unroll
            for (int j = 0; j < 8; j++) acc[j] = 0ull;
            #pragma unroll
            for (int kk = 0; kk < 32; kk += 2) {
                const int k = kb + kk;
                unsigned long long hv = pk2(hp[k*BB + b], hp[(k+1)*BB + b]);
                unsigned long long xv;
                if (l == 0) { float2 e = *(const float2*)(xp + k); xv = pk2(e.x, e.y); }
                else        xv = pk2(xp[k*BB + b], xp[(k+1)*BB + b]);
                #pragma unroll
                for (int j = 0; j < 8; j++) {
                    float2 wh = *(const float2*)&whh_s[j][k];
                    float2 wx = *(const float2*)&wih_s[j][k];
                    acc[j] = fma2(hv, pk2(wh.x, wh.y), acc[j]);
                    acc[j] = fma2(xv, pk2(wx.x, wx.y), acc[j]);
                }
            }
            #pragma unroll
            for (int j = 0; j < 8; j++) part[wi][j][b] = upks(acc[j]);
            __syncthreads();
            float p = bias_s[wi];
            #pragma unroll
            for (int w2 = 0; w2 < 8; w2++) p += part[w2][wi][b];
            g_h[l][(size_t)(t+1)*HB + (n0 + wi)*BB + b] = tanhf(p);
        }
        __syncthreads();
        if (tid == 0) {
            __threadfence();
            unsigned gen = *(volatile unsigned*)&g_bar_gen;
            if (atomicAdd(&g_bar_count, 1u) == NCTA - 1u) {
                g_bar_count = 0u;
                __threadfence();
                atomicAdd(&g_bar_gen, 1u);
            } else {
                while (*(volatile unsigned*)&g_bar_gen == gen) { }
            }
            __threadfence();
        }
        __syncthreads();
    }
    if (write_hidden)
        out_hidden[(size_t)l*BB*HH + (size_t)b*HH + (n0 + wi)] =
            g_h[l][(size_t)TT*HB + (n0 + wi)*BB + b];
}

// ================= Decoder: mma.sync bf16 GEMM (K=768) =================
// smem: 2 stages x (A 128x128B = 16KB, B 256x128B = 32KB) = 96KB
#define STG_A 16384
#define STG_B 32768
#define STG   (STG_A + STG_B)
#define SM_TOTAL (2 * STG)

__device__ __forceinline__ void load_stage(uint32_t smA, uint32_t smB, int kc,
                                           int m0, int n0, int tid) {
    const __nv_bfloat16* Ag = g_Aext;
    const __nv_bfloat16* Bg = g_Bext;
    #pragma unroll
    for (int i = 0; i < 4; i++) {               // A: 1024 16B chunks
        int l = tid + i * 256;
        int row = l >> 3, c = l & 7;
        const void* src = (const void*)(Ag + (size_t)(m0 + row) * DK + kc * DBK + c * 8);
        uint32_t dst = smA + row * 128 + ((c ^ (row & 7)) << 4);
        CP_ASYNC16(dst, src);
    }
    #pragma unroll
    for (int i = 0; i < 8; i++) {               // B: 2048 16B chunks
        int l = tid + i * 256;
        int row = l >> 3, c = l & 7;
        const void* src = (const void*)(Bg + (size_t)(n0 + row) * DK + kc * DBK + c * 8);
        uint32_t dst = smB + row * 128 + ((c ^ (row & 7)) << 4);
        CP_ASYNC16(dst, src);
    }
}

__global__ void __launch_bounds__(256, 1) dec_kernel(const float* __restrict__ dec_b,
                                                     float* __restrict__ out) {
    extern __shared__ char smem[];
    const uint32_t sbase = smem_u32(smem);
    const int tid = threadIdx.x;
    const int wid = tid >> 5, lane = tid & 31;
    const int m0 = blockIdx.x * DBM;
    const int n0 = blockIdx.y * DBN;
    const int wm = (wid & 1) * 64;
    const int wn = (wid >> 1) * 64;

    float acc[4][8][4];
    #pragma unroll
    for (int i = 0; i < 4; i++)
        #pragma unroll
        for (int j = 0; j < 8; j++)
            #pragma unroll
            for (int q = 0; q < 4; q++) acc[i][j][q] = 0.f;

    load_stage(sbase, sbase + STG_A, 0, m0, n0, tid);
    CP_COMMIT();

    #pragma unroll 1
    for (int kc = 0; kc < KITERS; kc++) {
        const uint32_t sA = sbase + (kc & 1) * STG;
        const uint32_t sB = sA + STG_A;
        if (kc + 1 < KITERS) {
            const uint32_t nA = sbase + ((kc + 1) & 1) * STG;
            load_stage(nA, nA + STG_A, kc + 1, m0, n0, tid);
            CP_COMMIT();
            CP_WAIT(1);
        } else {
            CP_WAIT(0);
        }
        __syncthreads();

        #pragma unroll
        for (int k16 = 0; k16 < 4; k16++) {
            uint32_t afr[4][4], bfr[4][4];
            #pragma unroll
            for (int mf = 0; mf < 4; mf++) {
                int rg = wm + mf * 16 + (lane & 15);
                int ch = k16 * 2 + (lane >> 4);
                uint32_t addr = sA + rg * 128 + ((ch ^ (rg & 7)) << 4);
                LDSM4(afr[mf][0], afr[mf][1], afr[mf][2], afr[mf][3], addr);
            }
            #pragma unroll
            for (int nf = 0; nf < 4; nf++) {
                int nr = wn + nf * 16 + (lane & 7) + ((lane >> 4) << 3);
                int ch = k16 * 2 + ((lane >> 3) & 1);
                uint32_t addr = sB + nr * 128 + ((ch ^ (nr & 7)) << 4);
                LDSM4(bfr[nf][0], bfr[nf][1], bfr[nf][2], bfr[nf][3], addr);
            }
            #pragma unroll
            for (int mf = 0; mf < 4; mf++)
                #pragma unroll
                for (int nf = 0; nf < 4; nf++) {
                    MMA16816(acc[mf][nf*2],   afr[mf], bfr[nf][0], bfr[nf][1]);
                    MMA16816(acc[mf][nf*2+1], afr[mf], bfr[nf][2], bfr[nf][3]);
                }
        }
        __syncthreads();
    }

    // epilogue: d-frag thread t -> rows (t/4, t/4+8), cols 2*(t%4)+{0,1}
    #pragma unroll
    for (int mf = 0; mf < 4; mf++) {
        const int r0 = m0 + wm + mf * 16 + (lane >> 2);
        #pragma unroll
        for (int nb = 0; nb < 8; nb++) {
            const int col = n0 + wn + nb * 8 + (lane & 3) * 2;
            float2 bb = *(const float2*)&dec_b[col];
            float2 s0 = { acc[mf][nb][0] + bb.x, acc[mf][nb][1] + bb.y };
            float2 s1 = { acc[mf][nb][2] + bb.x, acc[mf][nb][3] + bb.y };
            *(float2*)&out[(size_t)r0 * VV + col]       = s0;
            *(float2*)&out[(size_t)(r0 + 8) * VV + col] = s1;
        }
    }
}

extern "C" void kernel_launch(void* const* d_in, const int* in_sizes, int n_in,
                              void* d_out, int out_size) {
    const int*   tokens = (const int*)  d_in[0];
    const float* emb    = (const float*)d_in[1];
    const float* W_ih   = (const float*)d_in[2];
    const float* W_hh   = (const float*)d_in[3];
    const float* b_ih   = (const float*)d_in[4];
    const float* b_hh   = (const float*)d_in[5];
    const float* dec_W  = (const float*)d_in[6];
    const float* dec_b  = (const float*)d_in[7];
    float* out = (float*)d_out;

    const size_t dec_elems = (size_t)TT * BB * VV;
    const int write_hidden = ((size_t)out_size >= dec_elems + (size_t)LL*BB*HH) ? 1 : 0;
    float* out_hidden = out + dec_elems;

    cudaFuncSetAttribute(dec_kernel, cudaFuncAttributeMaxDynamicSharedMemorySize, SM_TOTAL);

    convW_kernel<<<2048, 256>>>(dec_W);
    rnn_kernel<<<NCTA, 256>>>(tokens, emb, W_ih, W_hh, b_ih, b_hh, out_hidden, write_hidden);
    convX_kernel<<<512, 256>>>();
    dim3 grid(MT, NT);
    dec_kernel<<<grid, 256, SM_TOTAL>>>(dec_b, out);
}

// round 5
// speedup vs baseline: 1.7851x; 1.1313x over previous
#include <cuda_runtime.h>
#include <cuda_bf16.h>
#include <cstdint>
#include <cstddef>

#define TT 256
#define BB 32
#define HH 256
#define LL 4
#define VV 32000
#define HB (HH*BB)
#define NCTA 128

#define DK   768          // extended K: [hi | lo | hi] x [hi | hi | lo]
#define DBM  128
#define DBN  256
#define DBK  64
#define KITERS (DK/DBK)   // 12
#define MT (8192/DBM)     // 64
#define NT (VV/DBN)       // 125

// ---------------- device scratch ----------------
__device__ float g_h[LL][(size_t)(TT+1)*HB];   // [l][t][k][b]; row t=0 stays zero
__device__ unsigned g_done[LL][TT+1];          // arrival counters, reset at kernel end
__device__ unsigned g_bar_count;               // final barrier (self-resetting)
__device__ unsigned g_bar_gen;                 // monotonic
__device__ __nv_bfloat16 g_Aext[(size_t)8192*DK];
__device__ __nv_bfloat16 g_Bext[(size_t)VV*DK];

// ---------------- helpers ----------------
__device__ __forceinline__ uint32_t smem_u32(const void* p) {
    uint32_t a;
    asm("{ .reg .u64 t; cvta.to.shared.u64 t, %1; cvt.u32.u64 %0, t; }" : "=r"(a) : "l"(p));
    return a;
}
#define CP_ASYNC16(dst, src) asm volatile("cp.async.cg.shared.global [%0], [%1], 16;" :: "r"(dst), "l"(src))
#define CP_COMMIT()          asm volatile("cp.async.commit_group;" ::: "memory")
#define CP_WAIT(n)           asm volatile("cp.async.wait_group %0;" :: "n"(n) : "memory")
#define LDSM4(r0,r1,r2,r3,addr) \
    asm volatile("ldmatrix.sync.aligned.m8n8.x4.shared.b16 {%0,%1,%2,%3}, [%4];" \
                 : "=r"(r0),"=r"(r1),"=r"(r2),"=r"(r3) : "r"(addr))
#define MMA16816(d, a, b0, b1) \
    asm volatile("mma.sync.aligned.m16n8k16.row.col.f32.bf16.bf16.f32 " \
                 "{%0,%1,%2,%3},{%4,%5,%6,%7},{%8,%9},{%0,%1,%2,%3};" \
                 : "+f"((d)[0]),"+f"((d)[1]),"+f"((d)[2]),"+f"((d)[3]) \
                 : "r"((a)[0]),"r"((a)[1]),"r"((a)[2]),"r"((a)[3]), "r"(b0),"r"(b1))

__device__ __forceinline__ void wait32(const unsigned* p) {
    unsigned v;
    do { asm volatile("ld.global.acquire.gpu.u32 %0, [%1];" : "=r"(v) : "l"(p)); } while (v < 32u);
}

// f32x2 helpers (RNN)
__device__ __forceinline__ unsigned long long pk2(float lo, float hi) {
    unsigned long long r;
    asm("mov.b64 %0, {%1, %2};" : "=l"(r) : "r"(__float_as_uint(lo)), "r"(__float_as_uint(hi)));
    return r;
}
__device__ __forceinline__ unsigned long long fma2(unsigned long long a, unsigned long long b,
                                                   unsigned long long c) {
    unsigned long long d;
    asm("fma.rn.f32x2 %0, %1, %2, %3;" : "=l"(d) : "l"(a), "l"(b), "l"(c));
    return d;
}
__device__ __forceinline__ float upks(unsigned long long v) {
    unsigned a, b;
    asm("mov.b64 {%0, %1}, %2;" : "=r"(a), "=r"(b) : "l"(v));
    return __uint_as_float(a) + __uint_as_float(b);
}

// ================= bf16-split conversions =================
__global__ void __launch_bounds__(256) convW_kernel(const float* __restrict__ W) {
    const size_t stride = (size_t)gridDim.x * 256;
    for (size_t e = (size_t)blockIdx.x * 256 + threadIdx.x; e < (size_t)VV * HH; e += stride) {
        const int k = (int)(e & 255);
        const size_t v = e >> 8;
        float w = W[e];
        __nv_bfloat16 hi = __float2bfloat16(w);
        __nv_bfloat16 lo = __float2bfloat16(w - __bfloat162float(hi));
        __nv_bfloat16* row = g_Bext + v * DK;
        row[k] = hi; row[256 + k] = hi; row[512 + k] = lo;
    }
}
__global__ void __launch_bounds__(256) convX_kernel() {
    const size_t stride = (size_t)gridDim.x * 256;
    for (size_t e = (size_t)blockIdx.x * 256 + threadIdx.x; e < (size_t)8192 * HH; e += stride) {
        const int m = (int)(e & 8191);
        const int k = (int)(e >> 13);
        const int t = m >> 5, b = m & 31;
        float x = g_h[LL-1][(size_t)(t + 1) * HB + k * BB + b];
        __nv_bfloat16 hi = __float2bfloat16(x);
        __nv_bfloat16 lo = __float2bfloat16(x - __bfloat162float(hi));
        __nv_bfloat16* row = g_Aext + (size_t)m * DK;
        row[k] = hi; row[256 + k] = lo; row[512 + k] = hi;
    }
}

// ================= RNN: dataflow-pipelined wavefront =================
// 128 CTAs = 4 layers x 32 n-slices. Per-(l,t) arrival counters; layers run async.
__global__ void __launch_bounds__(256) rnn_kernel(const int* __restrict__ tokens,
                                                  const float* __restrict__ emb,
                                                  const float* __restrict__ W_ih,
                                                  const float* __restrict__ W_hh,
                                                  const float* __restrict__ b_ih,
                                                  const float* __restrict__ b_hh,
                                                  float* out_hidden, int write_hidden) {
    const int cta = blockIdx.x;
    const int l = cta >> 5;
    const int n0 = (cta & 31) * 8;
    __shared__ float wih_s[8][HH], whh_s[8][HH];
    __shared__ float part[8][8][BB];
    __shared__ float bias_s[8];
    const int tid = threadIdx.x;

    for (int i = tid; i < 8*HH; i += 256) {
        int j = i / HH, k = i % HH;
        wih_s[j][k] = W_ih[((size_t)l*HH + n0 + j)*HH + k];
        whh_s[j][k] = W_hh[((size_t)l*HH + n0 + j)*HH + k];
    }
    if (tid < 8) bias_s[tid] = b_ih[l*HH + n0 + tid] + b_hh[l*HH + n0 + tid];
    __syncthreads();

    const int wi = tid >> 5, b = tid & 31;
    const int kb = wi * 32;

    for (int t = 0; t < TT; t++) {
        // wait for dependencies (dataflow; no global barrier)
        if (t > 0) wait32(&g_done[l][t]);          // own layer h(t-1), all 32 slices
        if (l > 0) wait32(&g_done[l-1][t+1]);      // lower layer x(t)

        const float* hp = g_h[l] + (size_t)t * HB;
        const float* xp;
        if (l == 0) xp = emb + (size_t)tokens[t*BB + b] * HH;
        else        xp = g_h[l-1] + (size_t)(t+1) * HB;
        unsigned long long acc[8];
        #pragma unroll
        for (int j = 0; j < 8; j++) acc[j] = 0ull;
        #pragma unroll
        for (int kk = 0; kk < 32; kk += 2) {
            const int k = kb + kk;
            unsigned long long hv = pk2(hp[k*BB + b], hp[(k+1)*BB + b]);
            unsigned long long xv;
            if (l == 0) { float2 e = *(const float2*)(xp + k); xv = pk2(e.x, e.y); }
            else        xv = pk2(xp[k*BB + b], xp[(k+1)*BB + b]);
            #pragma unroll
            for (int j = 0; j < 8; j++) {
                float2 wh = *(const float2*)&whh_s[j][k];
                float2 wx = *(const float2*)&wih_s[j][k];
                acc[j] = fma2(hv, pk2(wh.x, wh.y), acc[j]);
                acc[j] = fma2(xv, pk2(wx.x, wx.y), acc[j]);
            }
        }
        #pragma unroll
        for (int j = 0; j < 8; j++) part[wi][j][b] = upks(acc[j]);
        __syncthreads();
        float p = bias_s[wi];
        #pragma unroll
        for (int w2 = 0; w2 < 8; w2++) p += part[w2][wi][b];
        g_h[l][(size_t)(t+1)*HB + (n0 + wi)*BB + b] = tanhf(p);
        __syncthreads();
        if (tid == 0) {
            __threadfence();                        // release our slice
            atomicAdd(&g_done[l][t+1], 1u);
        }
        __syncthreads();
    }

    if (write_hidden)
        out_hidden[(size_t)l*BB*HH + (size_t)b*HH + (n0 + wi)] =
            g_h[l][(size_t)TT*HB + (n0 + wi)*BB + b];

    // ---- teardown: observe global completion, barrier, then reset counters ----
    wait32(&g_done[LL-1][TT]);
    __syncthreads();
    if (tid == 0) {
        unsigned gen = *(volatile unsigned*)&g_bar_gen;
        if (atomicAdd(&g_bar_count, 1u) == NCTA - 1u) {
            g_bar_count = 0u;
            __threadfence();
            atomicAdd(&g_bar_gen, 1u);
        } else {
            while (*(volatile unsigned*)&g_bar_gen == gen) { }
        }
        // all CTAs past observation point; safe to zero
        unsigned* cnt = &g_done[0][0];
        for (int i = cta; i < LL*(TT+1); i += NCTA) cnt[i] = 0u;
    }
}

// ================= Decoder: mma.sync bf16 GEMM (K=768), 3-stage pipeline =================
#define STG_A 16384
#define STG_B 32768
#define STG   (STG_A + STG_B)
#define NSTG  3
#define SM_TOTAL (NSTG * STG)

__device__ __forceinline__ void load_stage(uint32_t smA, uint32_t smB, int kc,
                                           int m0, int n0, int tid) {
    const __nv_bfloat16* Ag = g_Aext;
    const __nv_bfloat16* Bg = g_Bext;
    #pragma unroll
    for (int i = 0; i < 4; i++) {
        int l = tid + i * 256;
        int row = l >> 3, c = l & 7;
        const void* src = (const void*)(Ag + (size_t)(m0 + row) * DK + kc * DBK + c * 8);
        uint32_t dst = smA + row * 128 + ((c ^ (row & 7)) << 4);
        CP_ASYNC16(dst, src);
    }
    #pragma unroll
    for (int i = 0; i < 8; i++) {
        int l = tid + i * 256;
        int row = l >> 3, c = l & 7;
        const void* src = (const void*)(Bg + (size_t)(n0 + row) * DK + kc * DBK + c * 8);
        uint32_t dst = smB + row * 128 + ((c ^ (row & 7)) << 4);
        CP_ASYNC16(dst, src);
    }
}

__global__ void __launch_bounds__(256, 1) dec_kernel(const float* __restrict__ dec_b,
                                                     float* __restrict__ out) {
    extern __shared__ char smem[];
    const uint32_t sbase = smem_u32(smem);
    const int tid = threadIdx.x;
    const int wid = tid >> 5, lane = tid & 31;
    const int m0 = blockIdx.x * DBM;
    const int n0 = blockIdx.y * DBN;
    const int wm = (wid & 1) * 64;
    const int wn = (wid >> 1) * 64;

    float acc[4][8][4];
    #pragma unroll
    for (int i = 0; i < 4; i++)
        #pragma unroll
        for (int j = 0; j < 8; j++)
            #pragma unroll
            for (int q = 0; q < 4; q++) acc[i][j][q] = 0.f;

    load_stage(sbase, sbase + STG_A, 0, m0, n0, tid);
    CP_COMMIT();
    load_stage(sbase + STG, sbase + STG + STG_A, 1, m0, n0, tid);
    CP_COMMIT();

    #pragma unroll 1
    for (int kc = 0; kc < KITERS; kc++) {
        if (kc + 2 < KITERS) {
            const uint32_t nA = sbase + ((kc + 2) % NSTG) * STG;
            load_stage(nA, nA + STG_A, kc + 2, m0, n0, tid);
            CP_COMMIT();
            CP_WAIT(2);
        } else if (kc + 1 < KITERS) {
            CP_WAIT(1);
        } else {
            CP_WAIT(0);
        }
        __syncthreads();

        const uint32_t sA = sbase + (kc % NSTG) * STG;
        const uint32_t sB = sA + STG_A;
        #pragma unroll
        for (int k16 = 0; k16 < 4; k16++) {
            uint32_t afr[4][4], bfr[4][4];
            #pragma unroll
            for (int mf = 0; mf < 4; mf++) {
                int rg = wm + mf * 16 + (lane & 15);
                int ch = k16 * 2 + (lane >> 4);
                uint32_t addr = sA + rg * 128 + ((ch ^ (rg & 7)) << 4);
                LDSM4(afr[mf][0], afr[mf][1], afr[mf][2], afr[mf][3], addr);
            }
            #pragma unroll
            for (int nf = 0; nf < 4; nf++) {
                int nr = wn + nf * 16 + (lane & 7) + ((lane >> 4) << 3);
                int ch = k16 * 2 + ((lane >> 3) & 1);
                uint32_t addr = sB + nr * 128 + ((ch ^ (nr & 7)) << 4);
                LDSM4(bfr[nf][0], bfr[nf][1], bfr[nf][2], bfr[nf][3], addr);
            }
            #pragma unroll
            for (int mf = 0; mf < 4; mf++)
                #pragma unroll
                for (int nf = 0; nf < 4; nf++) {
                    MMA16816(acc[mf][nf*2],   afr[mf], bfr[nf][0], bfr[nf][1]);
                    MMA16816(acc[mf][nf*2+1], afr[mf], bfr[nf][2], bfr[nf][3]);
                }
        }
        __syncthreads();
    }

    #pragma unroll
    for (int mf = 0; mf < 4; mf++) {
        const int r0 = m0 + wm + mf * 16 + (lane >> 2);
        #pragma unroll
        for (int nb = 0; nb < 8; nb++) {
            const int col = n0 + wn + nb * 8 + (lane & 3) * 2;
            float2 bb = *(const float2*)&dec_b[col];
            float2 s0 = { acc[mf][nb][0] + bb.x, acc[mf][nb][1] + bb.y };
            float2 s1 = { acc[mf][nb][2] + bb.x, acc[mf][nb][3] + bb.y };
            *(float2*)&out[(size_t)r0 * VV + col]       = s0;
            *(float2*)&out[(size_t)(r0 + 8) * VV + col] = s1;
        }
    }
}

extern "C" void kernel_launch(void* const* d_in, const int* in_sizes, int n_in,
                              void* d_out, int out_size) {
    const int*   tokens = (const int*)  d_in[0];
    const float* emb    = (const float*)d_in[1];
    const float* W_ih   = (const float*)d_in[2];
    const float* W_hh   = (const float*)d_in[3];
    const float* b_ih   = (const float*)d_in[4];
    const float* b_hh   = (const float*)d_in[5];
    const float* dec_W  = (const float*)d_in[6];
    const float* dec_b  = (const float*)d_in[7];
    float* out = (float*)d_out;

    const size_t dec_elems = (size_t)TT * BB * VV;
    const int write_hidden = ((size_t)out_size >= dec_elems + (size_t)LL*BB*HH) ? 1 : 0;
    float* out_hidden = out + dec_elems;

    cudaFuncSetAttribute(dec_kernel, cudaFuncAttributeMaxDynamicSharedMemorySize, SM_TOTAL);

    convW_kernel<<<2048, 256>>>(dec_W);
    rnn_kernel<<<NCTA, 256>>>(tokens, emb, W_ih, W_hh, b_ih, b_hh, out_hidden, write_hidden);
    convX_kernel<<<512, 256>>>();
    dim3 grid(MT, NT);
    dec_kernel<<<grid, 256, SM_TOTAL>>>(dec_b, out);
}